// round 5
// baseline (speedup 1.0000x reference)
#include <cuda_runtime.h>
#include <cstdint>
#include <cfloat>

#define NH    218
#define NSUB  47524      // 218*218
#define NROWS 64         // B * C_OUT * C_IN = 2*8*4

// ---------------- device globals (no allocations allowed) ----------------
__device__ __align__(16) float2 g_Ws[32 * 12 * 16];   // [-2*Kstruct] packed perm-pairs: [o*4+i][pp][c16]
__device__ float    g_c2[32];                          // ||K||^2+||R||^2+||C||^2 per (o*4+i)
__device__ float2   g_rp[2 * 4 * 8 * 12 * 218];        // rpart: [b][i][o][pp][h1]
__device__ float2   g_cp[2 * 4 * 8 * 12 * 218];        // cpart: [b][i][o][pp][h2]
__device__ float    g_pmax[NROWS][NH];                 // per-(row, h1-block) max
__device__ float    g_psum[NROWS][NH];                 // per-(row, h1-block) sum of exp(m - blkmax)
__device__ float    g_fac[NROWS][NH];                  // exp(blkmax - gmx) / S
__device__ float    g_sims[(size_t)NROWS * NSUB];      // stores exp(m - blkmax)

__constant__ unsigned char c_P[24][4] = {
  {0,1,2,3},{0,1,3,2},{0,2,1,3},{0,2,3,1},{0,3,1,2},{0,3,2,1},
  {1,0,2,3},{1,0,3,2},{1,2,0,3},{1,2,3,0},{1,3,0,2},{1,3,2,0},
  {2,0,1,3},{2,0,3,1},{2,1,0,3},{2,1,3,0},{2,3,0,1},{2,3,1,0},
  {3,0,1,2},{3,0,2,1},{3,1,0,2},{3,1,2,0},{3,2,0,1},{3,2,1,0}
};

// ---------------- packed f32x2 helpers -----------------------------------
__device__ __forceinline__ unsigned long long dup2(float f) {
    unsigned long long r; unsigned u = __float_as_uint(f);
    asm("mov.b64 %0, {%1, %1};" : "=l"(r) : "r"(u));
    return r;
}
__device__ __forceinline__ unsigned long long add2(unsigned long long a, unsigned long long b) {
    unsigned long long r;
    asm("add.rn.f32x2 %0, %1, %2;" : "=l"(r) : "l"(a), "l"(b));
    return r;
}
#define FMA2(acc, x, w) asm("fma.rn.f32x2 %0, %1, %2, %0;" : "+l"(acc) : "l"(x), "l"(w))

// ---------------- prep 1: weights + c2 ------------------------------------
__global__ void prep_w_kernel(const float* __restrict__ ks,
                              const float* __restrict__ kr,
                              const float* __restrict__ kc) {
    int tid = threadIdx.x;
    if (tid < 32) {
        int oi = tid; float s = 0.0f;
        const float* a = ks + oi * 16;
        #pragma unroll
        for (int j = 0; j < 16; j++) s += a[j] * a[j];
        const float* r = kr + oi * 4; const float* c = kc + oi * 4;
        #pragma unroll
        for (int j = 0; j < 4; j++) { s += r[j] * r[j]; s += c[j] * c[j]; }
        g_c2[oi] = s;
    }
    for (int e = tid; e < 32 * 24 * 16; e += blockDim.x) {
        int c = e & 15; int t = e >> 4;
        int p = t % 24; int oi = t / 24;
        int a = c >> 2, bb = c & 3;
        float val = ks[oi * 16 + (int)c_P[p][a] * 4 + (int)c_P[p][bb]];
        ((float*)g_Ws)[((oi * 12 + (p >> 1)) * 16 + c) * 2 + (p & 1)] = -2.0f * val;
    }
}

// ---------------- prep 2: rp/cp tables ------------------------------------
__global__ void prep_tab_kernel(const float* __restrict__ types,
                                const float* __restrict__ kr,
                                const float* __restrict__ kc) {
    int idx = blockIdx.x, tid = threadIdx.x;
    int b = idx / NH, h = idx - b * NH;
    for (int e = tid; e < 768; e += blockDim.x) {
        int p = e % 24; int o = (e / 24) & 7; int i = e / 192;
        const float* tp = types + (b * 4 + i) * 224 + h;
        float t0 = tp[0], t1 = tp[2], t2 = tp[4], t3 = tp[6];
        float t2s = t0 * t0 + t1 * t1 + t2 * t2 + t3 * t3;
        const float* krp = kr + (o * 4 + i) * 4;
        const float* kcp = kc + (o * 4 + i) * 4;
        float rd = t0 * krp[c_P[p][0]] + t1 * krp[c_P[p][1]] + t2 * krp[c_P[p][2]] + t3 * krp[c_P[p][3]];
        float cd = t0 * kcp[c_P[p][0]] + t1 * kcp[c_P[p][1]] + t2 * kcp[c_P[p][2]] + t3 * kcp[c_P[p][3]];
        size_t lin = (size_t)(((b * 4 + i) * 8 + o) * 12 + (p >> 1)) * NH + h;
        ((float*)g_rp)[lin * 2 + (p & 1)] = t2s - 2.0f * rd;
        ((float*)g_cp)[lin * 2 + (p & 1)] = t2s - 2.0f * cd;
    }
}

// ---------------- prep 3: h_mean closed form -------------------------------
__global__ void prep_h_kernel(const float* __restrict__ feats, float* __restrict__ out) {
    int b = blockIdx.x, f = threadIdx.x;
    float acc = 0.0f;
    for (int n = 0; n < 224; n++) {
        int lo = (n >= NH) ? ((n - (NH - 2)) >> 1) : 0;
        int hi = min(3, n >> 1);
        acc += (float)(hi - lo + 1) * feats[(b * 224 + n) * 128 + f];
    }
    out[b * 128 + f] = acc * (2.0f / (float)NH);
}

// ---------------- sims: one block per h1 row; online softmax --------------
// block = 224 threads (h2 = tid), grid = (218, B, 2)  [LAUNCH #4 -> profiled]
__global__ void __launch_bounds__(224, 2)
sims_kernel(const float* __restrict__ graph) {
    __shared__ __align__(16) float2 sw[16 * 12 * 16];   // [oL*4+i][pp][c16]  (24.6 KB)
    __shared__ float2   srp[192];
    __shared__ float    sc2s[16];
    __shared__ unsigned smax[16];
    __shared__ float    smaxf[16];
    __shared__ float    ssum[16];

    int tid   = threadIdx.x;
    int b     = blockIdx.y;
    int oBase = blockIdx.z * 4;
    int h1    = blockIdx.x;

    {
        const float4* src = ((const float4*)g_Ws) + (size_t)oBase * 4 * 12 * 8;
        float4* dst = (float4*)sw;
        for (int e = tid; e < 16 * 12 * 8; e += 224) dst[e] = src[e];
        if (tid < 16) { sc2s[tid] = g_c2[oBase * 4 + tid]; smax[tid] = 0u; ssum[tid] = 0.0f; }
        if (tid < 192) {
            int i = tid / 48, oL = (tid / 12) & 3, pp = tid % 12;
            srp[tid] = g_rp[(size_t)((b * 32 + i * 8 + oBase + oL) * 12 + pp) * NH + h1];
        }
    }
    __syncthreads();

    int  h2    = tid;
    bool valid = h2 < NH;
    int  h2c   = valid ? h2 : (NH - 1);
    int  s     = h1 * NH + h2c;

    float mv[16];    // per-thread min-distance per local row (o*4+i)

    #pragma unroll 1
    for (int i = 0; i < 4; i++) {
        float xv[16];
        const float* gp = graph + (((b * 4 + i) * 224) + h1) * 224 + h2c;
        #pragma unroll
        for (int a = 0; a < 4; a++) {
            const float* rp = gp + (2 * a) * 224;
            #pragma unroll
            for (int bb = 0; bb < 4; bb++) xv[a * 4 + bb] = rp[2 * bb];
        }
        float x2 = 0.0f;
        #pragma unroll
        for (int c = 0; c < 16; c++) x2 = fmaf(xv[c], xv[c], x2);

        unsigned long long xd[16];
        #pragma unroll
        for (int c = 0; c < 16; c++) xd[c] = dup2(xv[c]);

        #pragma unroll 1
        for (int o = 0; o < 4; o++) {
            unsigned long long rc[12];
            {
                const unsigned long long* cpg =
                    (const unsigned long long*)(g_cp + (size_t)((b * 32 + i * 8 + oBase + o) * 12) * NH + h2c);
                const unsigned long long* rps =
                    (const unsigned long long*)(srp + (i * 4 + o) * 12);
                #pragma unroll
                for (int pp = 0; pp < 12; pp++)
                    rc[pp] = add2(cpg[(size_t)pp * NH], rps[pp]);
            }
            unsigned long long init2 = dup2(x2 + sc2s[o * 4 + i]);
            float m = FLT_MAX;
            const ulonglong2* wb = (const ulonglong2*)&sw[(o * 4 + i) * 192];
            #pragma unroll
            for (int pp = 0; pp < 12; pp += 2) {
                unsigned long long acc0 = add2(init2, rc[pp]);
                unsigned long long acc1 = add2(init2, rc[pp + 1]);
                const ulonglong2* w0 = wb + pp * 8;
                const ulonglong2* w1 = w0 + 8;
                #pragma unroll
                for (int cc = 0; cc < 8; cc++) {
                    ulonglong2 wa = w0[cc];
                    ulonglong2 wv = w1[cc];
                    FMA2(acc0, xd[2 * cc],     wa.x);
                    FMA2(acc0, xd[2 * cc + 1], wa.y);
                    FMA2(acc1, xd[2 * cc],     wv.x);
                    FMA2(acc1, xd[2 * cc + 1], wv.y);
                }
                float l0, h0, l1, hh1;
                asm("mov.b64 {%0, %1}, %2;" : "=f"(l0), "=f"(h0)  : "l"(acc0));
                asm("mov.b64 {%0, %1}, %2;" : "=f"(l1), "=f"(hh1) : "l"(acc1));
                m = fminf(m, fminf(fminf(l0, h0), fminf(l1, hh1)));
            }
            mv[o * 4 + i] = m;

            unsigned key = 0u;
            if (valid) {
                unsigned u = __float_as_uint(m);
                key = (u & 0x80000000u) ? ~u : (u | 0x80000000u);
            }
            unsigned kw = __reduce_max_sync(0xffffffffu, key);
            if ((tid & 31) == 0) atomicMax(&smax[o * 4 + i], kw);
        }
    }

    __syncthreads();
    if (tid < 16) {
        unsigned u = smax[tid];
        smaxf[tid] = (u & 0x80000000u) ? __uint_as_float(u & 0x7fffffffu)
                                       : __uint_as_float(~u);
    }
    __syncthreads();

    // phase 2: store e = exp(m - blkmax), accumulate block sums
    #pragma unroll 1
    for (int lr = 0; lr < 16; lr++) {
        int o = lr >> 2, i = lr & 3;
        int row = b * 32 + (oBase + o) * 4 + i;
        float e = valid ? __expf(mv[lr] - smaxf[lr]) : 0.0f;
        if (valid) g_sims[(size_t)row * NSUB + s] = e;
        float acc = e;
        #pragma unroll
        for (int off = 16; off; off >>= 1) acc += __shfl_xor_sync(0xffffffffu, acc, off);
        if ((tid & 31) == 0) atomicAdd(&ssum[lr], acc);
    }
    __syncthreads();
    if (tid < 16) {
        int o = tid >> 2, i = tid & 3;
        int row = b * 32 + (oBase + o) * 4 + i;
        g_pmax[row][h1] = smaxf[tid];
        g_psum[row][h1] = ssum[tid];
    }
}

// ---------------- combine: global max/sum + factor table -------------------
__global__ void combine_kernel() {
    __shared__ float red[256];
    int row = blockIdx.x, tid = threadIdx.x;
    float pm = (tid < NH) ? g_pmax[row][tid] : -FLT_MAX;
    red[tid] = pm; __syncthreads();
    #pragma unroll
    for (int st = 128; st; st >>= 1) {
        if (tid < st) red[tid] = fmaxf(red[tid], red[tid + st]);
        __syncthreads();
    }
    float gmx = red[0];
    __syncthreads();
    float ex = (tid < NH) ? __expf(pm - gmx) : 0.0f;
    red[tid] = (tid < NH) ? g_psum[row][tid] * ex : 0.0f;
    __syncthreads();
    #pragma unroll
    for (int st = 128; st; st >>= 1) {
        if (tid < st) red[tid] += red[tid + st];
        __syncthreads();
    }
    float S = red[0];
    if (tid < NH) g_fac[row][tid] = ex / S;
}

// ---------------- writeout: pure streaming multiply ------------------------
__global__ void writeout_kernel(float* __restrict__ out) {
    int h1 = blockIdx.x, row = blockIdx.y, tid = threadIdx.x;
    if (tid >= NH) return;
    float f = g_fac[row][h1];
    size_t idx = (size_t)row * NSUB + h1 * NH + tid;
    float e = g_sims[idx];
    out[256 + idx] = (1.0f - e * f) * (1.0f / (float)NSUB);
}

// ---------------- launch ---------------------------------------------------
extern "C" void kernel_launch(void* const* d_in, const int* in_sizes, int n_in,
                              void* d_out, int out_size) {
    const float* graph    = (const float*)d_in[0];
    const float* types    = (const float*)d_in[1];
    const float* features = (const float*)d_in[2];
    const float* ks       = (const float*)d_in[3];
    const float* kr       = (const float*)d_in[4];
    const float* kc       = (const float*)d_in[5];
    float* out = (float*)d_out;

    prep_w_kernel<<<1, 256>>>(ks, kr, kc);
    prep_tab_kernel<<<2 * NH, 256>>>(types, kr, kc);
    prep_h_kernel<<<2, 128>>>(features, out);
    sims_kernel<<<dim3(NH, 2, 2), 224>>>(graph);      // launch #4 -> ncu capture
    combine_kernel<<<NROWS, 256>>>();
    writeout_kernel<<<dim3(NH, NROWS), 224>>>(out);
}